// round 15
// baseline (speedup 1.0000x reference)
#include <cuda_runtime.h>
#include <math.h>

#define BATCH 1024
#define SEQ   200
#define EMB   128
#define TSTEPS 199
#define PW    640      // P columns: [K(128) | V(128) | KP(128) | Q2(128) | Q3(128)]
#define AST   204      // attn smem row stride (per head)
#define KPST  132      // KP smem row stride (per s)
#define NEGF  (-3.402823466e38f)

// ---------------- device scratch ----------------
__device__ float g_P[(size_t)BATCH * SEQ * PW];
__device__ float g_Wcat[EMB * PW];
__device__ float g_qhat[BATCH * EMB];
__device__ float g_qvec[2 * EMB];

// ---------------- build combined weights: [Wk | Wv | Wp@Wo^T | Wq2 | Wq3] -------
__global__ void wcat_kernel(const float* __restrict__ Wk, const float* __restrict__ Wv,
                            const float* __restrict__ Wo, const float* __restrict__ Wp,
                            const float* __restrict__ Wq) {
    int e = threadIdx.x;
    int c = blockIdx.x;
    float v;
    if (c < 128) {
        v = Wk[e * 128 + c];
    } else if (c < 256) {
        v = Wv[e * 128 + (c - 128)];
    } else if (c < 384) {
        int i = c - 256;
        float s = 0.f;
        for (int j = 0; j < 128; j++) s += Wp[e * 128 + j] * Wo[i * 128 + j];
        v = s;
    } else if (c < 512) {
        v = Wq[(128 + e) * 128 + (c - 384)];
    } else {
        v = Wq[(256 + e) * 128 + (c - 512)];
    }
    g_Wcat[e * PW + c] = v;
}

// ---------------- h_hat mean + qhat = h_hat @ Wq1 (+ vl/vf projections) ---------
__global__ void prep_kernel(const float* __restrict__ enc, const float* __restrict__ vl,
                            const float* __restrict__ vf, const float* __restrict__ Wq) {
    __shared__ float hh[EMB];
    int b = blockIdx.x, e = threadIdx.x;
    const float* p = enc + (size_t)b * SEQ * EMB + e;
    float s = 0.f;
    for (int i = 0; i < SEQ; i++) s += p[(size_t)i * EMB];
    hh[e] = s * (1.0f / (float)SEQ);
    __syncthreads();
    float q = 0.f;
    for (int k = 0; k < 128; k++) q += hh[k] * Wq[k * 128 + e];
    g_qhat[b * EMB + e] = q;
    if (b == 0) {
        float a = 0.f, c = 0.f;
        for (int k = 0; k < 128; k++) {
            a += vl[k] * Wq[(128 + k) * 128 + e];
            c += vf[k] * Wq[(256 + k) * 128 + e];
        }
        g_qvec[e] = a;
        g_qvec[128 + e] = c;
    }
}

// ---- SGEMM: 256x128 CTA tile, 8x8 microtile via packed fma.rn.f32x2 (FFMA2) ----
// grid = (5 n-blocks, 800 m-blocks): n fastest -> A tile L2-reused 5x
__global__ __launch_bounds__(512, 1) void gemm_kernel(const float* __restrict__ A) {
    extern __shared__ float smg[];
    float* As = smg;               // As[k*260 + m], m 0..255 (pad 4)
    float* Bs = smg + 128 * 260;   // Bs[k*128 + n]
    int m0 = blockIdx.y * 256, n0 = blockIdx.x * 128;
    int tid = threadIdx.x;
#pragma unroll
    for (int it = 0; it < 64; it++) {
        int idx = tid + it * 512;
        int k = idx & 127, m = idx >> 7;
        As[k * 260 + m] = A[(size_t)(m0 + m) * 128 + k];
    }
#pragma unroll
    for (int it = 0; it < 32; it++) {
        int idx = tid + it * 512;
        int n = idx & 127, k = idx >> 7;
        Bs[k * 128 + n] = g_Wcat[k * PW + n0 + n];
    }
    __syncthreads();
    int tx = tid & 15, ty = tid >> 4;
    // acc2[i][j2]: packed fp32x2 accumulators, j2 = n-pair index (bit-exact fp32)
    unsigned long long acc2[8][4];
#pragma unroll
    for (int i = 0; i < 8; i++)
#pragma unroll
        for (int j = 0; j < 4; j++) acc2[i][j] = 0ull;
#pragma unroll 4
    for (int k = 0; k < 128; k++) {
        float4 a0 = *(float4*)&As[k * 260 + ty * 8];
        float4 a1 = *(float4*)&As[k * 260 + ty * 8 + 4];
        // B pairs loaded as packed b64 (LDS.128 -> two f32x2 each)
        ulonglong2 bp0 = *(ulonglong2*)&Bs[k * 128 + tx * 8];
        ulonglong2 bp1 = *(ulonglong2*)&Bs[k * 128 + tx * 8 + 4];
        unsigned long long bpair[4] = {bp0.x, bp0.y, bp1.x, bp1.y};
        float av[8] = {a0.x, a0.y, a0.z, a0.w, a1.x, a1.y, a1.z, a1.w};
#pragma unroll
        for (int i = 0; i < 8; i++) {
            unsigned int au = __float_as_uint(av[i]);
            unsigned long long ad;
            asm("mov.b64 %0, {%1, %1};" : "=l"(ad) : "r"(au));
#pragma unroll
            for (int j = 0; j < 4; j++) {
                asm("fma.rn.f32x2 %0, %1, %2, %0;"
                    : "+l"(acc2[i][j]) : "l"(ad), "l"(bpair[j]));
            }
        }
    }
#pragma unroll
    for (int i = 0; i < 8; i++) {
        float r[8];
#pragma unroll
        for (int j = 0; j < 4; j++) {
            asm("mov.b64 {%0, %1}, %2;" : "=f"(r[2 * j]), "=f"(r[2 * j + 1]) : "l"(acc2[i][j]));
        }
        float* cr = &g_P[(size_t)(m0 + ty * 8 + i) * PW + n0 + tx * 8];
        *(float4*)cr       = make_float4(r[0], r[1], r[2], r[3]);
        *(float4*)(cr + 4) = make_float4(r[4], r[5], r[6], r[7]);
    }
}

// --- decode: frozen R14 (512 thr, K regs, V+KP SMEM, ffs mask-skip C) ---
__global__ __launch_bounds__(512) void decode_kernel(float* __restrict__ outLogits,
                                                     float* __restrict__ outLogp,
                                                     float* __restrict__ outSol) {
    extern __shared__ float sm[];
    float*    Vsm  = sm;                        // 200*128 = 25600
    float*    KPsm = Vsm + SEQ * 128;           // 200*132 = 26400
    float*    attn = KPsm + SEQ * KPST;         // 8*204 (unnormalized)
    float*    ctxp = attn + 8 * AST;            // 16*128
    float*    qv   = ctxp + 16 * 128;           // 128
    float*    ctx  = qv + EMB;                  // 128
    float*    wsum = ctx + EMB;                 // 16
    float*    redv = wsum + 16;                 // 16
    int*      redi = (int*)(redv + 16);         // 16
    float*    reds = (float*)(redi + 16);       // 2*16 double-buffered CE sums
    unsigned* maskw = (unsigned*)(reds + 32);   // 8
    int*      sols  = (int*)(maskw + 8);        // 200
    float*    s_logp = (float*)(sols + SEQ);    // 1

    int tid = threadIdx.x, lane = tid & 31, w = tid >> 5;
    int b = blockIdx.x;
    const float* __restrict__ Pb = g_P + (size_t)b * SEQ * PW;

    // ---- one-time SMEM fills: V row-major [s][128], KP row-major [s][132] ----
    for (int i = tid; i < SEQ * EMB; i += 512) {
        int s = i >> 7, e = i & 127;
        Vsm[s * 128 + e]   = Pb[(size_t)s * PW + 128 + e];
        KPsm[s * KPST + e] = Pb[(size_t)s * PW + 256 + e];
    }

    // ---- K in registers: warp w = (head h = w>>1, sub = w&1), 4 rows of s ----
    int h = w >> 1, sub = w & 1;
    float4 kreg[4][4];
#pragma unroll
    for (int r = 0; r < 4; r++) {
        int s = sub * 128 + (r << 5) + lane;
        if (s < SEQ) {
            const float4* kp = (const float4*)&Pb[(size_t)s * PW + (h << 4)];
            kreg[r][0] = kp[0]; kreg[r][1] = kp[1]; kreg[r][2] = kp[2]; kreg[r][3] = kp[3];
        } else {
            kreg[r][0] = kreg[r][1] = kreg[r][2] = kreg[r][3] = make_float4(0.f, 0.f, 0.f, 0.f);
        }
    }

    // C-phase window constants for this warp
    int s0 = w * 13;
    unsigned winvalid = (w == 15) ? ((1u << (SEQ - 15 * 13)) - 1u) : 0x1FFFu;

    float qhat_r = 0.f, q2r = 0.f, q3r = 0.f;
    if (tid < 128) {
        qhat_r = g_qhat[b * EMB + tid];
        q2r = g_qvec[tid];          // t=0: last = vl
        q3r = g_qvec[128 + tid];    // t=0: first = vf
        qv[tid] = (qhat_r + q2r + q3r) * 0.25f;   // initial q, pre-scaled 1/sqrt(dh)
    }
    if (tid < 8) maskw[tid] = (tid == 0) ? 1u : 0u;
    if (tid == 0) { *s_logp = 0.f; sols[0] = 0; }
    __syncthreads();

    const float inv_scale = 0.08838834764831845f;   // 1/sqrt(128)

    for (int t = 0; t < TSTEPS; t++) {
        // ---- [B] scores (register K) + fast exp + attn store + warp sum ----
        {
            const float4* qp = (const float4*)&qv[h << 4];
            float4 q0 = qp[0], q1 = qp[1], q2 = qp[2], q3 = qp[3];
            float ssum = 0.f;
#pragma unroll
            for (int r = 0; r < 4; r++) {
                int s = sub * 128 + (r << 5) + lane;
                float v;
                v  = q0.x * kreg[r][0].x + q0.y * kreg[r][0].y + q0.z * kreg[r][0].z + q0.w * kreg[r][0].w;
                v += q1.x * kreg[r][1].x + q1.y * kreg[r][1].y + q1.z * kreg[r][1].z + q1.w * kreg[r][1].w;
                v += q2.x * kreg[r][2].x + q2.y * kreg[r][2].y + q2.z * kreg[r][2].z + q2.w * kreg[r][2].w;
                v += q3.x * kreg[r][3].x + q3.y * kreg[r][3].y + q3.z * kreg[r][3].z + q3.w * kreg[r][3].w;
                bool ok = (s < SEQ) && !((maskw[4 * sub + r] >> lane) & 1u);
                float er = __expf(ok ? v : NEGF);   // masked/invalid -> 0 (MUFU.EX2 path)
                ssum += er;
                if (s < SEQ) attn[h * AST + s] = er;
            }
#pragma unroll
            for (int o = 16; o; o >>= 1) ssum += __shfl_xor_sync(0xffffffffu, ssum, o);
            if (lane == 0) wsum[w] = ssum;
        }
        __syncthreads();

        // ---- [C] ctx partials: ffs loop over UNMASKED s only (attn==0 skipped) ----
        {
            int hd = lane >> 2;
            const float* arow = &attn[hd * AST];
            unsigned long long mw =
                ((unsigned long long)maskw[(s0 >> 5) + 1] << 32) | maskw[s0 >> 5];
            unsigned win = (unsigned)((~mw) >> (s0 & 31)) & winvalid;
            float a0 = 0.f, a1 = 0.f, a2 = 0.f, a3 = 0.f;
            while (win) {
                int i = __ffs(win) - 1;
                win &= win - 1;
                int s = s0 + i;
                float a = arow[s];
                float4 vv = *(const float4*)&Vsm[s * 128 + (lane << 2)];
                a0 += a * vv.x; a1 += a * vv.y; a2 += a * vv.z; a3 += a * vv.w;
            }
            *(float4*)&ctxp[w * 128 + (lane << 2)] = make_float4(a0, a1, a2, a3);
        }
        __syncthreads();

        // ---- [D] ctx combine + softmax normalization ----
        if (tid < 128) {
            float s = 0.f;
#pragma unroll
            for (int i = 0; i < 16; i++) s += ctxp[i * 128 + tid];
            int hd = tid >> 4;
            ctx[tid] = s * (1.f / (wsum[2 * hd] + wsum[2 * hd + 1]));
        }
        __syncthreads();

        // ---- [E] pointer logits: 13 warps x 16 s + fast tanh + candidate prefetch ----
        float myval = NEGF;
        if (w < 13) {
            int sl = lane & 15, half = lane >> 4;
            int s = (w << 4) + sl;                // < 208; s>=200 gated below
            int sv = (s < SEQ) ? s : (SEQ - 1);
            const float* kp = &KPsm[sv * KPST + (half << 6)];
            const float* cx = &ctx[half << 6];
            float z0 = 0.f, z1 = 0.f, z2 = 0.f, z3 = 0.f;
#pragma unroll
            for (int j = 0; j < 16; j++) {
                float4 c4 = *(const float4*)&cx[j << 2];
                float4 k4 = *(const float4*)&kp[j << 2];
                z0 += c4.x * k4.x; z1 += c4.y * k4.y;
                z2 += c4.z * k4.z; z3 += c4.w * k4.w;
            }
            float z = (z0 + z1) + (z2 + z3);
            z += __shfl_xor_sync(0xffffffffu, z, 16);
            // u = 10*tanh(z/sqrt(E)) via fast exp: 10 - 20/(e^{2x}+1)
            float x2 = 2.f * (z * inv_scale);
            float u = 10.f - __fdividef(20.f, __expf(x2) + 1.f);
            bool valid = (s < SEQ);
            bool masked = valid ? ((maskw[s >> 5] >> (s & 31)) & 1u) : true;
            if (valid && half == 0) {
                outLogits[((size_t)b * TSTEPS + t) * SEQ + s] = u;
                if (!masked) myval = u;           // CE owner: one lane per s
            }
            float aval = masked ? NEGF : u;       // duplicated on both halves: harmless
            int vidx = valid ? s : 0x7fffffff;
#pragma unroll
            for (int o = 16; o; o >>= 1) {
                float ov = __shfl_xor_sync(0xffffffffu, aval, o);
                int   oi = __shfl_xor_sync(0xffffffffu, vidx, o);
                if (ov > aval || (ov == aval && oi < vidx)) { aval = ov; vidx = oi; }
            }
            if (lane == 0) { redv[w] = aval; redi[w] = vidx; }
            // block winner is among the 13 warp candidates: prefetch each
            // candidate's Q2 row into L2 so F's dependent gather is an L2 hit.
            if (vidx < SEQ) {
                if (lane < 4) {
                    const float* pf = &Pb[(size_t)vidx * PW + 384 + lane * 32];
                    asm volatile("prefetch.global.L2 [%0];" :: "l"(pf));
                }
                if (t == 0 && lane >= 4 && lane < 8) {
                    const float* pf = &Pb[(size_t)vidx * PW + 512 + (lane - 4) * 32];
                    asm volatile("prefetch.global.L2 [%0];" :: "l"(pf));
                }
            }
        }
        __syncthreads();

        // ---- [F] all-thread candidate scan + CE + mask + q gather + qv build ----
        {
            if (tid == 0 && t > 0) {
                const float* rp = &reds[((t - 1) & 1) * 16];
                float tot = 0.f;
#pragma unroll
                for (int i = 0; i < 13; i++) tot += rp[i];
                *s_logp += __logf(tot);
            }
            float bm = redv[0]; int bi = redi[0];
#pragma unroll
            for (int i = 1; i < 13; i++) {
                float v = redv[i];
                if (v > bm) { bm = v; bi = redi[i]; }
            }
            if (tid < 128) {
                q2r = Pb[(size_t)bi * PW + 384 + tid];             // Q2[b, idx] (L2 hit)
                if (t == 0) q3r = Pb[(size_t)bi * PW + 512 + tid]; // Q3[b, idx0]
            }
            if (w < 13) {
                float e = __expf(myval - bm);   // masked/non-owner -> 0
#pragma unroll
                for (int o = 16; o; o >>= 1) e += __shfl_xor_sync(0xffffffffu, e, o);
                if (lane == 0) reds[(t & 1) * 16 + w] = e;
            }
            if (tid == 0) {
                maskw[bi >> 5] |= (1u << (bi & 31));
                sols[t + 1] = bi;
            }
            if (tid < 128) qv[tid] = (qhat_r + q2r + q3r) * 0.25f;
        }
        __syncthreads();
    }

    if (tid == 0 && outLogp) {
        const float* rp = &reds[((TSTEPS - 1) & 1) * 16];
        float tot = 0.f;
        for (int i = 0; i < 13; i++) tot += rp[i];
        outLogp[b] = *s_logp + __logf(tot);
    }
    if (outSol && tid < SEQ) outSol[b * SEQ + tid] = (float)sols[tid];
}

// -------------------------------- launcher --------------------------------------
extern "C" void kernel_launch(void* const* d_in, const int* in_sizes, int n_in,
                              void* d_out, int out_size) {
    const float* enc = (const float*)d_in[0];
    const float* vl = (const float*)d_in[3];
    const float* vf = (const float*)d_in[4];
    const float* Wq = (const float*)d_in[5];
    const float* Wk = (const float*)d_in[6];
    const float* Wv = (const float*)d_in[7];
    const float* Wo = (const float*)d_in[8];
    const float* Wp = (const float*)d_in[9];

    float* out = (float*)d_out;
    size_t L = (size_t)BATCH * TSTEPS * SEQ;
    float* outLogp = nullptr;
    float* outSol  = nullptr;
    if ((size_t)out_size >= L + BATCH) outLogp = out + L;
    if ((size_t)out_size >= L + BATCH + (size_t)BATCH * SEQ) outSol = out + L + BATCH;

    const int gemm_smem = (128 * 260 + 128 * 128) * 4;   // 198,656 B
    const int decode_smem = 56232 * 4;                   // 224,928 B
    cudaFuncSetAttribute(gemm_kernel,   cudaFuncAttributeMaxDynamicSharedMemorySize, gemm_smem);
    cudaFuncSetAttribute(decode_kernel, cudaFuncAttributeMaxDynamicSharedMemorySize, decode_smem);

    wcat_kernel<<<PW, 128>>>(Wk, Wv, Wo, Wp, Wq);
    prep_kernel<<<BATCH, 128>>>(enc, vl, vf, Wq);
    gemm_kernel<<<dim3(PW / 128, BATCH * SEQ / 256), 512, gemm_smem>>>(enc);
    decode_kernel<<<BATCH, 512, decode_smem>>>(out, outLogp, outSol);
}

// round 16
// speedup vs baseline: 1.0044x; 1.0044x over previous
#include <cuda_runtime.h>
#include <math.h>

#define BATCH 1024
#define SEQ   200
#define EMB   128
#define TSTEPS 199
#define PW    640      // P columns: [K(128) | V(128) | KP(128) | Q2(128) | Q3(128)]
#define AST   204      // attn smem row stride (per head)
#define KPST  132      // KP smem row stride (per s)
#define NEGF  (-3.402823466e38f)

// ---------------- device scratch ----------------
__device__ float g_P[(size_t)BATCH * SEQ * PW];
__device__ float g_Wcat[EMB * PW];
__device__ float g_qhat[BATCH * EMB];
__device__ float g_qvec[2 * EMB];

// ---------------- build combined weights: [Wk | Wv | Wp@Wo^T | Wq2 | Wq3] -------
__global__ void wcat_kernel(const float* __restrict__ Wk, const float* __restrict__ Wv,
                            const float* __restrict__ Wo, const float* __restrict__ Wp,
                            const float* __restrict__ Wq) {
    int e = threadIdx.x;
    int c = blockIdx.x;
    float v;
    if (c < 128) {
        v = Wk[e * 128 + c];
    } else if (c < 256) {
        v = Wv[e * 128 + (c - 128)];
    } else if (c < 384) {
        int i = c - 256;
        float s = 0.f;
        for (int j = 0; j < 128; j++) s += Wp[e * 128 + j] * Wo[i * 128 + j];
        v = s;
    } else if (c < 512) {
        v = Wq[(128 + e) * 128 + (c - 384)];
    } else {
        v = Wq[(256 + e) * 128 + (c - 512)];
    }
    g_Wcat[e * PW + c] = v;
}

// ---------------- h_hat mean + qhat = h_hat @ Wq1 (+ vl/vf projections) ---------
__global__ void prep_kernel(const float* __restrict__ enc, const float* __restrict__ vl,
                            const float* __restrict__ vf, const float* __restrict__ Wq) {
    __shared__ float hh[EMB];
    int b = blockIdx.x, e = threadIdx.x;
    const float* p = enc + (size_t)b * SEQ * EMB + e;
    float s = 0.f;
    for (int i = 0; i < SEQ; i++) s += p[(size_t)i * EMB];
    hh[e] = s * (1.0f / (float)SEQ);
    __syncthreads();
    float q = 0.f;
    for (int k = 0; k < 128; k++) q += hh[k] * Wq[k * 128 + e];
    g_qhat[b * EMB + e] = q;
    if (b == 0) {
        float a = 0.f, c = 0.f;
        for (int k = 0; k < 128; k++) {
            a += vl[k] * Wq[(128 + k) * 128 + e];
            c += vf[k] * Wq[(256 + k) * 128 + e];
        }
        g_qvec[e] = a;
        g_qvec[128 + e] = c;
    }
}

// ---- SGEMM: 256x128 CTA tile, 8x8 microtile via packed fma.rn.f32x2 (FFMA2) ----
__global__ __launch_bounds__(512, 1) void gemm_kernel(const float* __restrict__ A) {
    extern __shared__ float smg[];
    float* As = smg;               // As[k*260 + m], m 0..255 (pad 4)
    float* Bs = smg + 128 * 260;   // Bs[k*128 + n]
    int m0 = blockIdx.y * 256, n0 = blockIdx.x * 128;
    int tid = threadIdx.x;
#pragma unroll
    for (int it = 0; it < 64; it++) {
        int idx = tid + it * 512;
        int k = idx & 127, m = idx >> 7;
        As[k * 260 + m] = A[(size_t)(m0 + m) * 128 + k];
    }
#pragma unroll
    for (int it = 0; it < 32; it++) {
        int idx = tid + it * 512;
        int n = idx & 127, k = idx >> 7;
        Bs[k * 128 + n] = g_Wcat[k * PW + n0 + n];
    }
    __syncthreads();
    int tx = tid & 15, ty = tid >> 4;
    unsigned long long acc2[8][4];
#pragma unroll
    for (int i = 0; i < 8; i++)
#pragma unroll
        for (int j = 0; j < 4; j++) acc2[i][j] = 0ull;
#pragma unroll 4
    for (int k = 0; k < 128; k++) {
        float4 a0 = *(float4*)&As[k * 260 + ty * 8];
        float4 a1 = *(float4*)&As[k * 260 + ty * 8 + 4];
        ulonglong2 bp0 = *(ulonglong2*)&Bs[k * 128 + tx * 8];
        ulonglong2 bp1 = *(ulonglong2*)&Bs[k * 128 + tx * 8 + 4];
        unsigned long long bpair[4] = {bp0.x, bp0.y, bp1.x, bp1.y};
        float av[8] = {a0.x, a0.y, a0.z, a0.w, a1.x, a1.y, a1.z, a1.w};
#pragma unroll
        for (int i = 0; i < 8; i++) {
            unsigned int au = __float_as_uint(av[i]);
            unsigned long long ad;
            asm("mov.b64 %0, {%1, %1};" : "=l"(ad) : "r"(au));
#pragma unroll
            for (int j = 0; j < 4; j++) {
                asm("fma.rn.f32x2 %0, %1, %2, %0;"
                    : "+l"(acc2[i][j]) : "l"(ad), "l"(bpair[j]));
            }
        }
    }
#pragma unroll
    for (int i = 0; i < 8; i++) {
        float r[8];
#pragma unroll
        for (int j = 0; j < 4; j++) {
            asm("mov.b64 {%0, %1}, %2;" : "=f"(r[2 * j]), "=f"(r[2 * j + 1]) : "l"(acc2[i][j]));
        }
        float* cr = &g_P[(size_t)(m0 + ty * 8 + i) * PW + n0 + tx * 8];
        *(float4*)cr       = make_float4(r[0], r[1], r[2], r[3]);
        *(float4*)(cr + 4) = make_float4(r[4], r[5], r[6], r[7]);
    }
}

// --- decode: R14 structure; C and E inner products via bit-exact packed FMA2 ---
__global__ __launch_bounds__(512) void decode_kernel(float* __restrict__ outLogits,
                                                     float* __restrict__ outLogp,
                                                     float* __restrict__ outSol) {
    extern __shared__ float sm[];
    float*    Vsm  = sm;                        // 200*128 = 25600
    float*    KPsm = Vsm + SEQ * 128;           // 200*132 = 26400
    float*    attn = KPsm + SEQ * KPST;         // 8*204 (unnormalized)
    float*    ctxp = attn + 8 * AST;            // 16*128
    float*    qv   = ctxp + 16 * 128;           // 128
    float*    ctx  = qv + EMB;                  // 128
    float*    wsum = ctx + EMB;                 // 16
    float*    redv = wsum + 16;                 // 16
    int*      redi = (int*)(redv + 16);         // 16
    float*    reds = (float*)(redi + 16);       // 2*16 double-buffered CE sums
    unsigned* maskw = (unsigned*)(reds + 32);   // 8
    int*      sols  = (int*)(maskw + 8);        // 200
    float*    s_logp = (float*)(sols + SEQ);    // 1

    int tid = threadIdx.x, lane = tid & 31, w = tid >> 5;
    int b = blockIdx.x;
    const float* __restrict__ Pb = g_P + (size_t)b * SEQ * PW;

    // ---- one-time SMEM fills: V row-major [s][128], KP row-major [s][132] ----
    for (int i = tid; i < SEQ * EMB; i += 512) {
        int s = i >> 7, e = i & 127;
        Vsm[s * 128 + e]   = Pb[(size_t)s * PW + 128 + e];
        KPsm[s * KPST + e] = Pb[(size_t)s * PW + 256 + e];
    }

    // ---- K in registers: warp w = (head h = w>>1, sub = w&1), 4 rows of s ----
    int h = w >> 1, sub = w & 1;
    float4 kreg[4][4];
#pragma unroll
    for (int r = 0; r < 4; r++) {
        int s = sub * 128 + (r << 5) + lane;
        if (s < SEQ) {
            const float4* kp = (const float4*)&Pb[(size_t)s * PW + (h << 4)];
            kreg[r][0] = kp[0]; kreg[r][1] = kp[1]; kreg[r][2] = kp[2]; kreg[r][3] = kp[3];
        } else {
            kreg[r][0] = kreg[r][1] = kreg[r][2] = kreg[r][3] = make_float4(0.f, 0.f, 0.f, 0.f);
        }
    }

    // C-phase window constants for this warp
    int s0 = w * 13;
    unsigned winvalid = (w == 15) ? ((1u << (SEQ - 15 * 13)) - 1u) : 0x1FFFu;

    float qhat_r = 0.f, q2r = 0.f, q3r = 0.f;
    if (tid < 128) {
        qhat_r = g_qhat[b * EMB + tid];
        q2r = g_qvec[tid];          // t=0: last = vl
        q3r = g_qvec[128 + tid];    // t=0: first = vf
        qv[tid] = (qhat_r + q2r + q3r) * 0.25f;   // initial q, pre-scaled 1/sqrt(dh)
    }
    if (tid < 8) maskw[tid] = (tid == 0) ? 1u : 0u;
    if (tid == 0) { *s_logp = 0.f; sols[0] = 0; }
    __syncthreads();

    const float inv_scale = 0.08838834764831845f;   // 1/sqrt(128)

    for (int t = 0; t < TSTEPS; t++) {
        // ---- [B] scores (register K) + fast exp + attn store + warp sum ----
        {
            const float4* qp = (const float4*)&qv[h << 4];
            float4 q0 = qp[0], q1 = qp[1], q2 = qp[2], q3 = qp[3];
            float ssum = 0.f;
#pragma unroll
            for (int r = 0; r < 4; r++) {
                int s = sub * 128 + (r << 5) + lane;
                float v;
                v  = q0.x * kreg[r][0].x + q0.y * kreg[r][0].y + q0.z * kreg[r][0].z + q0.w * kreg[r][0].w;
                v += q1.x * kreg[r][1].x + q1.y * kreg[r][1].y + q1.z * kreg[r][1].z + q1.w * kreg[r][1].w;
                v += q2.x * kreg[r][2].x + q2.y * kreg[r][2].y + q2.z * kreg[r][2].z + q2.w * kreg[r][2].w;
                v += q3.x * kreg[r][3].x + q3.y * kreg[r][3].y + q3.z * kreg[r][3].z + q3.w * kreg[r][3].w;
                bool ok = (s < SEQ) && !((maskw[4 * sub + r] >> lane) & 1u);
                float er = __expf(ok ? v : NEGF);   // masked/invalid -> 0 (MUFU.EX2 path)
                ssum += er;
                if (s < SEQ) attn[h * AST + s] = er;
            }
#pragma unroll
            for (int o = 16; o; o >>= 1) ssum += __shfl_xor_sync(0xffffffffu, ssum, o);
            if (lane == 0) wsum[w] = ssum;
        }
        __syncthreads();

        // ---- [C] ctx partials: ffs loop over UNMASKED s, packed FMA2 (bit-exact) ----
        {
            int hd = lane >> 2;
            const float* arow = &attn[hd * AST];
            unsigned long long mw =
                ((unsigned long long)maskw[(s0 >> 5) + 1] << 32) | maskw[s0 >> 5];
            unsigned win = (unsigned)((~mw) >> (s0 & 31)) & winvalid;
            unsigned long long accp0 = 0ull, accp1 = 0ull;   // (a0,a1), (a2,a3)
            while (win) {
                int i = __ffs(win) - 1;
                win &= win - 1;
                int s = s0 + i;
                float a = arow[s];
                unsigned long long ad;
                asm("mov.b64 %0, {%1, %1};" : "=l"(ad) : "r"(__float_as_uint(a)));
                ulonglong2 v2 = *(const ulonglong2*)&Vsm[s * 128 + (lane << 2)];
                asm("fma.rn.f32x2 %0, %1, %2, %0;" : "+l"(accp0) : "l"(ad), "l"(v2.x));
                asm("fma.rn.f32x2 %0, %1, %2, %0;" : "+l"(accp1) : "l"(ad), "l"(v2.y));
            }
            ulonglong2 outv; outv.x = accp0; outv.y = accp1;
            *(ulonglong2*)&ctxp[w * 128 + (lane << 2)] = outv;
        }
        __syncthreads();

        // ---- [D] ctx combine + softmax normalization ----
        if (tid < 128) {
            float s = 0.f;
#pragma unroll
            for (int i = 0; i < 16; i++) s += ctxp[i * 128 + tid];
            int hd = tid >> 4;
            ctx[tid] = s * (1.f / (wsum[2 * hd] + wsum[2 * hd + 1]));
        }
        __syncthreads();

        // ---- [E] pointer logits: 13 warps x 16 s, packed FMA2 (bit-exact) ----
        float myval = NEGF;
        if (w < 13) {
            int sl = lane & 15, half = lane >> 4;
            int s = (w << 4) + sl;                // < 208; s>=200 gated below
            int sv = (s < SEQ) ? s : (SEQ - 1);
            const ulonglong2* kp2 = (const ulonglong2*)&KPsm[sv * KPST + (half << 6)];
            const ulonglong2* cx2 = (const ulonglong2*)&ctx[half << 6];
            unsigned long long acc0 = 0ull, acc1 = 0ull;   // (z0,z1), (z2,z3)
#pragma unroll
            for (int j = 0; j < 16; j++) {
                ulonglong2 c2 = cx2[j];
                ulonglong2 k2 = kp2[j];
                asm("fma.rn.f32x2 %0, %1, %2, %0;" : "+l"(acc0) : "l"(c2.x), "l"(k2.x));
                asm("fma.rn.f32x2 %0, %1, %2, %0;" : "+l"(acc1) : "l"(c2.y), "l"(k2.y));
            }
            float z0, z1, z2, z3;
            asm("mov.b64 {%0, %1}, %2;" : "=f"(z0), "=f"(z1) : "l"(acc0));
            asm("mov.b64 {%0, %1}, %2;" : "=f"(z2), "=f"(z3) : "l"(acc1));
            float z = (z0 + z1) + (z2 + z3);
            z += __shfl_xor_sync(0xffffffffu, z, 16);
            // u = 10*tanh(z/sqrt(E)) via fast exp: 10 - 20/(e^{2x}+1)
            float x2 = 2.f * (z * inv_scale);
            float u = 10.f - __fdividef(20.f, __expf(x2) + 1.f);
            bool valid = (s < SEQ);
            bool masked = valid ? ((maskw[s >> 5] >> (s & 31)) & 1u) : true;
            if (valid && half == 0) {
                outLogits[((size_t)b * TSTEPS + t) * SEQ + s] = u;
                if (!masked) myval = u;           // CE owner: one lane per s
            }
            float aval = masked ? NEGF : u;       // duplicated on both halves: harmless
            int vidx = valid ? s : 0x7fffffff;
#pragma unroll
            for (int o = 16; o; o >>= 1) {
                float ov = __shfl_xor_sync(0xffffffffu, aval, o);
                int   oi = __shfl_xor_sync(0xffffffffu, vidx, o);
                if (ov > aval || (ov == aval && oi < vidx)) { aval = ov; vidx = oi; }
            }
            if (lane == 0) { redv[w] = aval; redi[w] = vidx; }
            // block winner is among the 13 warp candidates: prefetch each
            // candidate's Q2 row into L2 so F's dependent gather is an L2 hit.
            if (vidx < SEQ) {
                if (lane < 4) {
                    const float* pf = &Pb[(size_t)vidx * PW + 384 + lane * 32];
                    asm volatile("prefetch.global.L2 [%0];" :: "l"(pf));
                }
                if (t == 0 && lane >= 4 && lane < 8) {
                    const float* pf = &Pb[(size_t)vidx * PW + 512 + (lane - 4) * 32];
                    asm volatile("prefetch.global.L2 [%0];" :: "l"(pf));
                }
            }
        }
        __syncthreads();

        // ---- [F] all-thread candidate scan + CE + mask + q gather + qv build ----
        {
            if (tid == 0 && t > 0) {
                const float* rp = &reds[((t - 1) & 1) * 16];
                float tot = 0.f;
#pragma unroll
                for (int i = 0; i < 13; i++) tot += rp[i];
                *s_logp += __logf(tot);
            }
            float bm = redv[0]; int bi = redi[0];
#pragma unroll
            for (int i = 1; i < 13; i++) {
                float v = redv[i];
                if (v > bm) { bm = v; bi = redi[i]; }
            }
            if (tid < 128) {
                q2r = Pb[(size_t)bi * PW + 384 + tid];             // Q2[b, idx] (L2 hit)
                if (t == 0) q3r = Pb[(size_t)bi * PW + 512 + tid]; // Q3[b, idx0]
            }
            if (w < 13) {
                float e = __expf(myval - bm);   // masked/non-owner -> 0
#pragma unroll
                for (int o = 16; o; o >>= 1) e += __shfl_xor_sync(0xffffffffu, e, o);
                if (lane == 0) reds[(t & 1) * 16 + w] = e;
            }
            if (tid == 0) {
                maskw[bi >> 5] |= (1u << (bi & 31));
                sols[t + 1] = bi;
            }
            if (tid < 128) qv[tid] = (qhat_r + q2r + q3r) * 0.25f;
        }
        __syncthreads();
    }

    if (tid == 0 && outLogp) {
        const float* rp = &reds[((TSTEPS - 1) & 1) * 16];
        float tot = 0.f;
        for (int i = 0; i < 13; i++) tot += rp[i];
        outLogp[b] = *s_logp + __logf(tot);
    }
    if (outSol && tid < SEQ) outSol[b * SEQ + tid] = (float)sols[tid];
}

// -------------------------------- launcher --------------------------------------
extern "C" void kernel_launch(void* const* d_in, const int* in_sizes, int n_in,
                              void* d_out, int out_size) {
    const float* enc = (const float*)d_in[0];
    const float* vl = (const float*)d_in[3];
    const float* vf = (const float*)d_in[4];
    const float* Wq = (const float*)d_in[5];
    const float* Wk = (const float*)d_in[6];
    const float* Wv = (const float*)d_in[7];
    const float* Wo = (const float*)d_in[8];
    const float* Wp = (const float*)d_in[9];

    float* out = (float*)d_out;
    size_t L = (size_t)BATCH * TSTEPS * SEQ;
    float* outLogp = nullptr;
    float* outSol  = nullptr;
    if ((size_t)out_size >= L + BATCH) outLogp = out + L;
    if ((size_t)out_size >= L + BATCH + (size_t)BATCH * SEQ) outSol = out + L + BATCH;

    const int gemm_smem = (128 * 260 + 128 * 128) * 4;   // 198,656 B
    const int decode_smem = 56232 * 4;                   // 224,928 B
    cudaFuncSetAttribute(gemm_kernel,   cudaFuncAttributeMaxDynamicSharedMemorySize, gemm_smem);
    cudaFuncSetAttribute(decode_kernel, cudaFuncAttributeMaxDynamicSharedMemorySize, decode_smem);

    wcat_kernel<<<PW, 128>>>(Wk, Wv, Wo, Wp, Wq);
    prep_kernel<<<BATCH, 128>>>(enc, vl, vf, Wq);
    gemm_kernel<<<dim3(PW / 128, BATCH * SEQ / 256), 512, gemm_smem>>>(enc);
    decode_kernel<<<BATCH, 512, decode_smem>>>(out, outLogp, outSol);
}